// round 1
// baseline (speedup 1.0000x reference)
#include <cuda_runtime.h>
#include <math.h>

// Problem constants
#define NB    4
#define CIN   1024
#define CINT  512
#define HH    96
#define WW    96
#define PP    (HH * WW)      // 9216
#define DD    4
#define QQ    81             // (2D+1)^2

// ---------------------------------------------------------------------------
// Scratch buffers (device globals — no allocation allowed)
// ---------------------------------------------------------------------------
__device__ float g_theta[NB * CINT * PP];
__device__ float g_gbuf [NB * CINT * PP];
__device__ float g_phi  [NB * CINT * PP];
__device__ float g_pw   [NB * QQ   * PP];
__device__ float g_y    [NB * CINT * PP];

// ---------------------------------------------------------------------------
// SGEMM: O[b][m][p] = sum_k W[m][k] * Z[b][k][p] + bias[m] (+ res[b][m][p])
// W row-major [M,K]; Z per-batch row-major [K,P]; O per-batch [M,P].
// Requires M%128==0, P%128==0, K%8==0 (true for all uses here).
// ---------------------------------------------------------------------------
#define BM 128
#define BN 128
#define BK 8
#define TM 8
#define TN 8

__global__ void __launch_bounds__(256)
sgemm_kernel(const float* __restrict__ W, const float* __restrict__ Z,
             const float* __restrict__ bias, const float* __restrict__ res,
             float* __restrict__ O, int M, int K, int P)
{
    __shared__ float As[BK][BM];
    __shared__ float Bs[BK][BN];

    const int b  = blockIdx.z;
    const float* Zb = Z + (size_t)b * K * P;
    float*       Ob = O + (size_t)b * M * P;
    const float* Rb = res ? res + (size_t)b * M * P : nullptr;

    const int m0 = blockIdx.y * BM;
    const int n0 = blockIdx.x * BN;
    const int tid = threadIdx.x;

    // A tile loads: 128 rows x 8 k. 2 threads/row, one float4 each.
    const int arow = tid >> 1;
    const int acol = (tid & 1) * 4;
    // B tile loads: 8 rows x 128 cols. 32 threads/row, one float4 each.
    const int brow = tid >> 5;
    const int bcol = (tid & 31) * 4;

    const int tx = tid & 15;
    const int ty = tid >> 4;

    float acc[TM][TN];
#pragma unroll
    for (int i = 0; i < TM; i++)
#pragma unroll
        for (int j = 0; j < TN; j++) acc[i][j] = 0.f;

    for (int k0 = 0; k0 < K; k0 += BK) {
        float4 av = *(const float4*)&W[(size_t)(m0 + arow) * K + k0 + acol];
        As[acol + 0][arow] = av.x;
        As[acol + 1][arow] = av.y;
        As[acol + 2][arow] = av.z;
        As[acol + 3][arow] = av.w;

        float4 bv = *(const float4*)&Zb[(size_t)(k0 + brow) * P + n0 + bcol];
        *(float4*)&Bs[brow][bcol] = bv;

        __syncthreads();

#pragma unroll
        for (int kk = 0; kk < BK; kk++) {
            float ra[TM], rb[TN];
#pragma unroll
            for (int i = 0; i < TM; i++) ra[i] = As[kk][ty * TM + i];
#pragma unroll
            for (int j = 0; j < TN; j++) rb[j] = Bs[kk][tx * TN + j];
#pragma unroll
            for (int i = 0; i < TM; i++)
#pragma unroll
                for (int j = 0; j < TN; j++) acc[i][j] += ra[i] * rb[j];
        }
        __syncthreads();
    }

    // Epilogue: bias (+ residual), vectorized stores
#pragma unroll
    for (int i = 0; i < TM; i++) {
        const int m = m0 + ty * TM + i;
        const float bv = bias[m];
        const size_t rowoff = (size_t)m * P + n0 + tx * TN;
#pragma unroll
        for (int j4 = 0; j4 < TN; j4 += 4) {
            float4 v;
            v.x = acc[i][j4 + 0] + bv;
            v.y = acc[i][j4 + 1] + bv;
            v.z = acc[i][j4 + 2] + bv;
            v.w = acc[i][j4 + 3] + bv;
            if (Rb) {
                float4 r = *(const float4*)&Rb[rowoff + j4];
                v.x += r.x; v.y += r.y; v.z += r.z; v.w += r.w;
            }
            *(float4*)&Ob[rowoff + j4] = v;
        }
    }
}

// ---------------------------------------------------------------------------
// Correlation + fused softmax.
// Tile: 32 (w) x 8 (h) pixels, one thread per pixel, 81 register accumulators.
// pw[b][q][p] = softmax_q( scale * sum_c theta[b][c][p] * phi[b][c][p+disp_q] )
// ---------------------------------------------------------------------------
#define CTW 32
#define CTH 8
#define CWIN_W (CTW + 2 * DD)   // 40
#define CWIN_H (CTH + 2 * DD)   // 16
#define CCH 4                   // channels per smem chunk

__global__ void __launch_bounds__(256)
corr_softmax_kernel(const float* __restrict__ theta,
                    const float* __restrict__ phi,
                    float* __restrict__ pw)
{
    __shared__ float th_s[CCH * CTH * CTW];            // [cc][r][col]
    __shared__ float ph_s[CCH * CWIN_H * CWIN_W];      // [cc][r][col]

    const int b  = blockIdx.z;
    const int w0 = blockIdx.x * CTW;
    const int h0 = blockIdx.y * CTH;
    const int tid = threadIdx.x;
    const int tx = tid & 31;
    const int ty = tid >> 5;

    const float* thb = theta + (size_t)b * CINT * PP;
    const float* phb = phi   + (size_t)b * CINT * PP;

    float acc[QQ];
#pragma unroll
    for (int q = 0; q < QQ; q++) acc[q] = 0.f;

    for (int c0 = 0; c0 < CINT; c0 += CCH) {
        // load theta tile (CCH channels x 8 x 32 = 1024 floats)
        for (int i = tid; i < CCH * CTH * CTW; i += 256) {
            const int cc  = i >> 8;            // / 256
            const int rem = i & 255;
            const int r   = rem >> 5;
            const int col = rem & 31;
            th_s[i] = thb[(size_t)(c0 + cc) * PP + (h0 + r) * WW + (w0 + col)];
        }
        // load phi window (CCH x 16 x 40 = 2560 floats, zero-padded)
        for (int i = tid; i < CCH * CWIN_H * CWIN_W; i += 256) {
            const int cc  = i / (CWIN_H * CWIN_W);
            const int rem = i % (CWIN_H * CWIN_W);
            const int r   = rem / CWIN_W;
            const int col = rem % CWIN_W;
            const int hh = h0 - DD + r;
            const int ww = w0 - DD + col;
            float v = 0.f;
            if (hh >= 0 && hh < HH && ww >= 0 && ww < WW)
                v = phb[(size_t)(c0 + cc) * PP + hh * WW + ww];
            ph_s[i] = v;
        }
        __syncthreads();

#pragma unroll
        for (int cc = 0; cc < CCH; cc++) {
            const float t = th_s[cc * (CTH * CTW) + ty * CTW + tx];
            const float* pr = &ph_s[cc * (CWIN_H * CWIN_W)];
#pragma unroll
            for (int dy = 0; dy < 9; dy++)
#pragma unroll
                for (int dx = 0; dx < 9; dx++)
                    acc[dy * 9 + dx] += t * pr[(ty + dy) * CWIN_W + (tx + dx)];
        }
        __syncthreads();
    }

    // fused softmax over q
    const float scale = (256.0f / sqrtf((float)WW)) / (float)CINT;
    float m = -1e30f;
#pragma unroll
    for (int q = 0; q < QQ; q++) { acc[q] *= scale; m = fmaxf(m, acc[q]); }
    float s = 0.f;
#pragma unroll
    for (int q = 0; q < QQ; q++) { acc[q] = __expf(acc[q] - m); s += acc[q]; }
    const float inv = 1.0f / s;

    float* pwb = pw + (size_t)b * QQ * PP;
    const int pix = (h0 + ty) * WW + (w0 + tx);
#pragma unroll
    for (int q = 0; q < QQ; q++) pwb[(size_t)q * PP + pix] = acc[q] * inv;
}

// ---------------------------------------------------------------------------
// Assemble: y[b][c][p] = sum_q pw[b][q][p] * g_pad[b][c][p+disp_q]
// Same tiling; pw vector lives in registers, g window streamed via smem.
// ---------------------------------------------------------------------------
__global__ void __launch_bounds__(256)
assemble_kernel(const float* __restrict__ pw,
                const float* __restrict__ g,
                float* __restrict__ y)
{
    __shared__ float gs[CCH * CWIN_H * CWIN_W];

    const int b  = blockIdx.z;
    const int w0 = blockIdx.x * CTW;
    const int h0 = blockIdx.y * CTH;
    const int tid = threadIdx.x;
    const int tx = tid & 31;
    const int ty = tid >> 5;

    const float* gb  = g  + (size_t)b * CINT * PP;
    const float* pwb = pw + (size_t)b * QQ * PP;
    float*       yb  = y  + (size_t)b * CINT * PP;

    const int pix = (h0 + ty) * WW + (w0 + tx);

    float rpw[QQ];
#pragma unroll
    for (int q = 0; q < QQ; q++) rpw[q] = pwb[(size_t)q * PP + pix];

    for (int c0 = 0; c0 < CINT; c0 += CCH) {
        for (int i = tid; i < CCH * CWIN_H * CWIN_W; i += 256) {
            const int cc  = i / (CWIN_H * CWIN_W);
            const int rem = i % (CWIN_H * CWIN_W);
            const int r   = rem / CWIN_W;
            const int col = rem % CWIN_W;
            const int hh = h0 - DD + r;
            const int ww = w0 - DD + col;
            float v = 0.f;
            if (hh >= 0 && hh < HH && ww >= 0 && ww < WW)
                v = gb[(size_t)(c0 + cc) * PP + hh * WW + ww];
            gs[i] = v;
        }
        __syncthreads();

#pragma unroll
        for (int cc = 0; cc < CCH; cc++) {
            const float* gr = &gs[cc * (CWIN_H * CWIN_W)];
            float a = 0.f;
#pragma unroll
            for (int dy = 0; dy < 9; dy++)
#pragma unroll
                for (int dx = 0; dx < 9; dx++)
                    a += rpw[dy * 9 + dx] * gr[(ty + dy) * CWIN_W + (tx + dx)];
            yb[(size_t)(c0 + cc) * PP + pix] = a;
        }
        __syncthreads();
    }
}

// ---------------------------------------------------------------------------
// Launch
// ---------------------------------------------------------------------------
extern "C" void kernel_launch(void* const* d_in, const int* in_sizes, int n_in,
                              void* d_out, int out_size)
{
    (void)in_sizes; (void)n_in; (void)out_size;

    const float* x       = (const float*)d_in[0];
    const float* x_ref   = (const float*)d_in[1];
    const float* w_g     = (const float*)d_in[2];
    const float* b_g     = (const float*)d_in[3];
    const float* w_theta = (const float*)d_in[4];
    const float* b_theta = (const float*)d_in[5];
    const float* w_phi   = (const float*)d_in[6];
    const float* b_phi   = (const float*)d_in[7];
    const float* w_out   = (const float*)d_in[8];
    const float* b_out   = (const float*)d_in[9];
    float* out = (float*)d_out;

    float *theta, *gbuf, *phi, *pw, *y;
    cudaGetSymbolAddress((void**)&theta, g_theta);
    cudaGetSymbolAddress((void**)&gbuf,  g_gbuf);
    cudaGetSymbolAddress((void**)&phi,   g_phi);
    cudaGetSymbolAddress((void**)&pw,    g_pw);
    cudaGetSymbolAddress((void**)&y,     g_y);

    dim3 blk(256);

    // 1x1 convs: theta(x), g(x_ref), phi(x_ref)
    dim3 gemm_grid(PP / BN, CINT / BM, NB);   // (72, 4, 4)
    sgemm_kernel<<<gemm_grid, blk>>>(w_theta, x,     b_theta, nullptr, theta, CINT, CIN, PP);
    sgemm_kernel<<<gemm_grid, blk>>>(w_g,     x_ref, b_g,     nullptr, gbuf,  CINT, CIN, PP);
    sgemm_kernel<<<gemm_grid, blk>>>(w_phi,   x_ref, b_phi,   nullptr, phi,   CINT, CIN, PP);

    // correlation + softmax
    dim3 corr_grid(WW / CTW, HH / CTH, NB);   // (3, 12, 4)
    corr_softmax_kernel<<<corr_grid, blk>>>(theta, phi, pw);

    // assemble
    assemble_kernel<<<corr_grid, blk>>>(pw, gbuf, y);

    // final conv + residual
    dim3 out_grid(PP / BN, CIN / BM, NB);     // (72, 8, 4)
    sgemm_kernel<<<out_grid, blk>>>(w_out, y, b_out, x, out, CIN, CINT, PP);
}

// round 2
// speedup vs baseline: 4.1371x; 4.1371x over previous
#include <cuda_runtime.h>
#include <cuda_bf16.h>
#include <math.h>
#include <stdint.h>

// Problem constants
#define NB    4
#define CIN   1024
#define CINT  512
#define HH    96
#define WW    96
#define PP    (HH * WW)      // 9216
#define DD    4
#define QQ    81
#define CSPLIT 4             // corr channel split
#define ASPLIT 8             // assemble channel split

// ---------------------------------------------------------------------------
// Scratch (device globals; no allocation allowed)
// ---------------------------------------------------------------------------
__device__ __align__(128) __nv_bfloat16 g_xb   [NB * CIN  * PP];
__device__ __align__(128) __nv_bfloat16 g_xrefb[NB * CIN  * PP];
__device__ __align__(128) __nv_bfloat16 g_wb   [4 * CINT * CIN];   // theta,g,phi,out
__device__ __align__(128) float g_theta [NB * CINT * PP];
__device__ __align__(128) float g_g     [NB * CINT * PP];
__device__ __align__(128) float g_phi   [NB * CINT * PP];
__device__ __align__(128) float g_pwpart[CSPLIT * NB * QQ * PP];
__device__ __align__(128) float g_pw    [NB * QQ * PP];
__device__ __align__(128) __nv_bfloat16 g_yb   [NB * CINT * PP];

// ---------------------------------------------------------------------------
// Helpers
// ---------------------------------------------------------------------------
__device__ __forceinline__ uint32_t sptr(const void* p) {
    return (uint32_t)__cvta_generic_to_shared(p);
}
__device__ __forceinline__ void cp16(uint32_t dst, const void* src) {
    asm volatile("cp.async.cg.shared.global [%0], [%1], 16;" :: "r"(dst), "l"(src));
}
__device__ __forceinline__ void cp_commit() {
    asm volatile("cp.async.commit_group;");
}
__device__ __forceinline__ void cp_wait0() {
    asm volatile("cp.async.wait_group 0;");
}
__device__ __forceinline__ void ldsmx4(uint32_t* r, uint32_t addr) {
    asm volatile("ldmatrix.sync.aligned.m8n8.x4.shared.b16 {%0,%1,%2,%3}, [%4];"
                 : "=r"(r[0]), "=r"(r[1]), "=r"(r[2]), "=r"(r[3]) : "r"(addr));
}
__device__ __forceinline__ void ldsmx4t(uint32_t* r, uint32_t addr) {
    asm volatile("ldmatrix.sync.aligned.m8n8.x4.trans.shared.b16 {%0,%1,%2,%3}, [%4];"
                 : "=r"(r[0]), "=r"(r[1]), "=r"(r[2]), "=r"(r[3]) : "r"(addr));
}
__device__ __forceinline__ void mma16816(float* c, const uint32_t* a, const uint32_t* b) {
    asm volatile("mma.sync.aligned.m16n8k16.row.col.f32.bf16.bf16.f32 "
                 "{%0,%1,%2,%3}, {%4,%5,%6,%7}, {%8,%9}, {%0,%1,%2,%3};"
                 : "+f"(c[0]), "+f"(c[1]), "+f"(c[2]), "+f"(c[3])
                 : "r"(a[0]), "r"(a[1]), "r"(a[2]), "r"(a[3]), "r"(b[0]), "r"(b[1]));
}

// ---------------------------------------------------------------------------
// fp32 -> bf16 conversion (n multiple of 8)
// ---------------------------------------------------------------------------
__global__ void __launch_bounds__(256)
f2bf_kernel(const float* __restrict__ in, __nv_bfloat16* __restrict__ out, int n)
{
    int i = (blockIdx.x * 256 + threadIdx.x) * 8;
    if (i >= n) return;
    float4 v0 = *(const float4*)(in + i);
    float4 v1 = *(const float4*)(in + i + 4);
    __nv_bfloat162 o[4];
    o[0] = __floats2bfloat162_rn(v0.x, v0.y);
    o[1] = __floats2bfloat162_rn(v0.z, v0.w);
    o[2] = __floats2bfloat162_rn(v1.x, v1.y);
    o[3] = __floats2bfloat162_rn(v1.z, v1.w);
    *(uint4*)(out + i) = *(const uint4*)o;
}

// ---------------------------------------------------------------------------
// bf16 tensor-core GEMM:
// O[b][m][p] = sum_k W[m][k]*Z[b][k][p] + bias[m] (+ res[b][m][p])
// BM=BN=128, BK=32, 8 warps (2m x 4n), warp tile 64x32, mma m16n8k16.
// ---------------------------------------------------------------------------
#define AS_STRIDE 40     // bf16 elems per A row (32 + 8 pad)
#define BS_STRIDE 136    // bf16 elems per B row (128 + 8 pad)
#define AS_ELEMS (128 * AS_STRIDE)
#define BS_ELEMS (32 * BS_STRIDE)
#define AS_BYTES (AS_ELEMS * 2)
#define BS_BYTES (BS_ELEMS * 2)

__global__ void __launch_bounds__(256)
bgemm_kernel(const __nv_bfloat16* __restrict__ W, const __nv_bfloat16* __restrict__ Z,
             const float* __restrict__ bias, const float* __restrict__ res,
             float* __restrict__ O, int M, int K, int P)
{
    __shared__ __nv_bfloat16 As[2 * AS_ELEMS];
    __shared__ __nv_bfloat16 Bs[2 * BS_ELEMS];

    const int b  = blockIdx.z;
    const __nv_bfloat16* Zb = Z + (size_t)b * K * P;
    float*       Ob = O + (size_t)b * M * P;
    const float* Rb = res ? res + (size_t)b * M * P : nullptr;

    const int m0 = blockIdx.y * 128;
    const int n0 = blockIdx.x * 128;
    const int tid  = threadIdx.x;
    const int lane = tid & 31;
    const int wid  = tid >> 5;
    const int wm = wid & 1;       // 2 warps in m
    const int wn = wid >> 1;      // 4 warps in n

    const uint32_t as0 = sptr(As);
    const uint32_t bs0 = sptr(Bs);

    // A loads: rows (tid>>2) and (tid>>2)+64, chunk (tid&3)
    const int a_r = tid >> 2;
    const int a_c = tid & 3;
    // B loads: rows (tid>>4) and (tid>>4)+16, chunk (tid&15)
    const int b_r = tid >> 4;
    const int b_c = tid & 15;

    float acc[4][4][4];
#pragma unroll
    for (int mt = 0; mt < 4; mt++)
#pragma unroll
        for (int nt = 0; nt < 4; nt++)
#pragma unroll
            for (int i = 0; i < 4; i++) acc[mt][nt][i] = 0.f;

    const int nk = K >> 5;

    // prologue: stage 0
    {
        const int k0 = 0;
        cp16(as0 + (uint32_t)((a_r)      * AS_STRIDE + a_c * 8) * 2, W  + (size_t)(m0 + a_r)      * K + k0 + a_c * 8);
        cp16(as0 + (uint32_t)((a_r + 64) * AS_STRIDE + a_c * 8) * 2, W  + (size_t)(m0 + a_r + 64) * K + k0 + a_c * 8);
        cp16(bs0 + (uint32_t)((b_r)      * BS_STRIDE + b_c * 8) * 2, Zb + (size_t)(k0 + b_r)      * P + n0 + b_c * 8);
        cp16(bs0 + (uint32_t)((b_r + 16) * BS_STRIDE + b_c * 8) * 2, Zb + (size_t)(k0 + b_r + 16) * P + n0 + b_c * 8);
        cp_commit();
    }

    int stage = 0;
    for (int kt = 0; kt < nk; kt++) {
        cp_wait0();
        __syncthreads();

        if (kt + 1 < nk) {
            const int k0 = (kt + 1) * 32;
            const uint32_t as = as0 + (stage ^ 1) * AS_BYTES;
            const uint32_t bs = bs0 + (stage ^ 1) * BS_BYTES;
            cp16(as + (uint32_t)((a_r)      * AS_STRIDE + a_c * 8) * 2, W  + (size_t)(m0 + a_r)      * K + k0 + a_c * 8);
            cp16(as + (uint32_t)((a_r + 64) * AS_STRIDE + a_c * 8) * 2, W  + (size_t)(m0 + a_r + 64) * K + k0 + a_c * 8);
            cp16(bs + (uint32_t)((b_r)      * BS_STRIDE + b_c * 8) * 2, Zb + (size_t)(k0 + b_r)      * P + n0 + b_c * 8);
            cp16(bs + (uint32_t)((b_r + 16) * BS_STRIDE + b_c * 8) * 2, Zb + (size_t)(k0 + b_r + 16) * P + n0 + b_c * 8);
            cp_commit();
        }

        const uint32_t as = as0 + stage * AS_BYTES;
        const uint32_t bs = bs0 + stage * BS_BYTES;

#pragma unroll
        for (int kk = 0; kk < 2; kk++) {
            const int k0 = kk * 16;
            uint32_t a[4][4];
            const uint32_t a_base = as + (uint32_t)(((wm * 64 + (lane & 15)) * AS_STRIDE) + k0 + (lane >> 4) * 8) * 2;
#pragma unroll
            for (int mt = 0; mt < 4; mt++)
                ldsmx4(a[mt], a_base + (uint32_t)(mt * 16 * AS_STRIDE) * 2);

            uint32_t bb[4][2];
            const uint32_t b_base = bs + (uint32_t)((k0 + (lane & 15)) * BS_STRIDE + wn * 32 + (lane >> 4) * 8) * 2;
            {
                uint32_t r[4];
                ldsmx4t(r, b_base);
                bb[0][0] = r[0]; bb[0][1] = r[1];
                bb[1][0] = r[2]; bb[1][1] = r[3];
                ldsmx4t(r, b_base + 16 * 2);
                bb[2][0] = r[0]; bb[2][1] = r[1];
                bb[3][0] = r[2]; bb[3][1] = r[3];
            }

#pragma unroll
            for (int mt = 0; mt < 4; mt++)
#pragma unroll
                for (int nt = 0; nt < 4; nt++)
                    mma16816(acc[mt][nt], a[mt], bb[nt]);
        }
        stage ^= 1;
        __syncthreads();
    }

    // epilogue
#pragma unroll
    for (int mt = 0; mt < 4; mt++) {
        const int r0 = m0 + wm * 64 + mt * 16 + (lane >> 2);
        const int r1 = r0 + 8;
        const float bv0 = bias[r0];
        const float bv1 = bias[r1];
#pragma unroll
        for (int nt = 0; nt < 4; nt++) {
            const int col = n0 + wn * 32 + nt * 8 + (lane & 3) * 2;
            float2 v0 = make_float2(acc[mt][nt][0] + bv0, acc[mt][nt][1] + bv0);
            float2 v1 = make_float2(acc[mt][nt][2] + bv1, acc[mt][nt][3] + bv1);
            if (Rb) {
                float2 t0 = *(const float2*)&Rb[(size_t)r0 * P + col];
                float2 t1 = *(const float2*)&Rb[(size_t)r1 * P + col];
                v0.x += t0.x; v0.y += t0.y;
                v1.x += t1.x; v1.y += t1.y;
            }
            *(float2*)&Ob[(size_t)r0 * P + col] = v0;
            *(float2*)&Ob[(size_t)r1 * P + col] = v1;
        }
    }
}

// ---------------------------------------------------------------------------
// Correlation (channel-split 4-way, partial logits, no softmax here)
// Tile 32x8 pixels, 1 thread/pixel, 81 accumulators. CCH=8 channels/iter.
// ---------------------------------------------------------------------------
#define CTW 32
#define CTH 8
#define CWIN_W (CTW + 2 * DD)   // 40
#define CWIN_H (CTH + 2 * DD)   // 16
#define CCH 8
#define CPB (CINT / CSPLIT)     // 128 channels per block

__global__ void __launch_bounds__(256, 2)
corr_kernel(const float* __restrict__ theta,
            const float* __restrict__ phi,
            float* __restrict__ pwpart)
{
    __shared__ float th_s[CCH * CTH * CTW];        // 8KB
    __shared__ float ph_s[CCH * CWIN_H * CWIN_W];  // 20KB

    const int z  = blockIdx.z;
    const int b  = z >> 2;
    const int ci = z & 3;
    const int ch0 = ci * CPB;
    const int w0 = blockIdx.x * CTW;
    const int h0 = blockIdx.y * CTH;
    const int tid = threadIdx.x;
    const int tx = tid & 31;
    const int ty = tid >> 5;

    const float* thb = theta + (size_t)b * CINT * PP;
    const float* phb = phi   + (size_t)b * CINT * PP;

    float acc[QQ];
#pragma unroll
    for (int q = 0; q < QQ; q++) acc[q] = 0.f;

    for (int c0 = ch0; c0 < ch0 + CPB; c0 += CCH) {
#pragma unroll
        for (int ii = 0; ii < (CCH * CTH * CTW) / 256; ii++) {
            const int i   = tid + ii * 256;
            const int cc  = i >> 8;
            const int rem = i & 255;
            const int r   = rem >> 5;
            const int col = rem & 31;
            th_s[i] = thb[(size_t)(c0 + cc) * PP + (h0 + r) * WW + (w0 + col)];
        }
#pragma unroll
        for (int ii = 0; ii < (CCH * CWIN_H * CWIN_W) / 256; ii++) {
            const int i   = tid + ii * 256;
            const int cc  = i / (CWIN_H * CWIN_W);
            const int rem = i % (CWIN_H * CWIN_W);
            const int r   = rem / CWIN_W;
            const int col = rem % CWIN_W;
            const int hh = h0 - DD + r;
            const int ww = w0 - DD + col;
            float v = 0.f;
            if (hh >= 0 && hh < HH && ww >= 0 && ww < WW)
                v = phb[(size_t)(c0 + cc) * PP + hh * WW + ww];
            ph_s[i] = v;
        }
        __syncthreads();

#pragma unroll
        for (int cc = 0; cc < CCH; cc++) {
            const float t = th_s[cc * (CTH * CTW) + ty * CTW + tx];
            const float* pr = &ph_s[cc * (CWIN_H * CWIN_W)];
#pragma unroll
            for (int dy = 0; dy < 9; dy++)
#pragma unroll
                for (int dx = 0; dx < 9; dx++)
                    acc[dy * 9 + dx] += t * pr[(ty + dy) * CWIN_W + (tx + dx)];
        }
        __syncthreads();
    }

    const int pix = (h0 + ty) * WW + (w0 + tx);
    float* base = pwpart + ((size_t)(ci * NB + b) * QQ) * PP + pix;
#pragma unroll
    for (int q = 0; q < QQ; q++) base[(size_t)q * PP] = acc[q];
}

// ---------------------------------------------------------------------------
// Softmax over Q (sums the 4 channel-split partials, applies scale)
// ---------------------------------------------------------------------------
__global__ void __launch_bounds__(128)
softmax_kernel(const float* __restrict__ part, float* __restrict__ pw)
{
    const int t = blockIdx.x * 128 + threadIdx.x;   // NB*PP threads
    const int b = t / PP;
    const int pix = t - b * PP;
    const size_t qp = (size_t)QQ * PP;
    const float scale = 256.0f / sqrtf((float)WW) / (float)CINT;

    float v[QQ];
    float m = -1e30f;
#pragma unroll
    for (int q = 0; q < QQ; q++) {
        const size_t off = (size_t)q * PP + pix;
        float s = part[(size_t)(0 * NB + b) * qp + off]
                + part[(size_t)(1 * NB + b) * qp + off]
                + part[(size_t)(2 * NB + b) * qp + off]
                + part[(size_t)(3 * NB + b) * qp + off];
        v[q] = s * scale;
        m = fmaxf(m, v[q]);
    }
    float s = 0.f;
#pragma unroll
    for (int q = 0; q < QQ; q++) { v[q] = __expf(v[q] - m); s += v[q]; }
    const float inv = 1.0f / s;
    float* pwb = pw + (size_t)b * qp + pix;
#pragma unroll
    for (int q = 0; q < QQ; q++) pwb[(size_t)q * PP] = v[q] * inv;
}

// ---------------------------------------------------------------------------
// Assemble (channel-split 8-way): y[b][c][p] = sum_q pw[b][q][p]*g_pad window
// Writes y in bf16 (consumed by final GEMM).
// ---------------------------------------------------------------------------
__global__ void __launch_bounds__(256, 2)
assemble_kernel(const float* __restrict__ pw,
                const float* __restrict__ g,
                __nv_bfloat16* __restrict__ y)
{
    __shared__ float gs[CCH * CWIN_H * CWIN_W];   // 20KB

    const int z  = blockIdx.z;
    const int b  = z >> 3;
    const int c0base = (z & 7) * (CINT / ASPLIT); // 64 channels
    const int w0 = blockIdx.x * CTW;
    const int h0 = blockIdx.y * CTH;
    const int tid = threadIdx.x;
    const int tx = tid & 31;
    const int ty = tid >> 5;

    const float* gb  = g  + (size_t)b * CINT * PP;
    const float* pwb = pw + (size_t)b * QQ * PP;
    __nv_bfloat16* yb = y + (size_t)b * CINT * PP;

    const int pix = (h0 + ty) * WW + (w0 + tx);

    float rpw[QQ];
#pragma unroll
    for (int q = 0; q < QQ; q++) rpw[q] = pwb[(size_t)q * PP + pix];

    for (int c0 = c0base; c0 < c0base + CINT / ASPLIT; c0 += CCH) {
#pragma unroll
        for (int ii = 0; ii < (CCH * CWIN_H * CWIN_W) / 256; ii++) {
            const int i   = tid + ii * 256;
            const int cc  = i / (CWIN_H * CWIN_W);
            const int rem = i % (CWIN_H * CWIN_W);
            const int r   = rem / CWIN_W;
            const int col = rem % CWIN_W;
            const int hh = h0 - DD + r;
            const int ww = w0 - DD + col;
            float v = 0.f;
            if (hh >= 0 && hh < HH && ww >= 0 && ww < WW)
                v = gb[(size_t)(c0 + cc) * PP + hh * WW + ww];
            gs[i] = v;
        }
        __syncthreads();

#pragma unroll
        for (int cc = 0; cc < CCH; cc++) {
            const float* gr = &gs[cc * (CWIN_H * CWIN_W)];
            float a = 0.f;
#pragma unroll
            for (int dy = 0; dy < 9; dy++)
#pragma unroll
                for (int dx = 0; dx < 9; dx++)
                    a += rpw[dy * 9 + dx] * gr[(ty + dy) * CWIN_W + (tx + dx)];
            yb[(size_t)(c0 + cc) * PP + pix] = __float2bfloat16(a);
        }
        __syncthreads();
    }
}

// ---------------------------------------------------------------------------
// Launch
// ---------------------------------------------------------------------------
extern "C" void kernel_launch(void* const* d_in, const int* in_sizes, int n_in,
                              void* d_out, int out_size)
{
    (void)in_sizes; (void)n_in; (void)out_size;

    const float* x       = (const float*)d_in[0];
    const float* x_ref   = (const float*)d_in[1];
    const float* w_g     = (const float*)d_in[2];
    const float* b_g     = (const float*)d_in[3];
    const float* w_theta = (const float*)d_in[4];
    const float* b_theta = (const float*)d_in[5];
    const float* w_phi   = (const float*)d_in[6];
    const float* b_phi   = (const float*)d_in[7];
    const float* w_out   = (const float*)d_in[8];
    const float* b_out   = (const float*)d_in[9];
    float* out = (float*)d_out;

    __nv_bfloat16 *xb, *xrefb, *wb, *yb;
    float *theta, *gbuf, *phi, *pwpart, *pw;
    cudaGetSymbolAddress((void**)&xb,     g_xb);
    cudaGetSymbolAddress((void**)&xrefb,  g_xrefb);
    cudaGetSymbolAddress((void**)&wb,     g_wb);
    cudaGetSymbolAddress((void**)&theta,  g_theta);
    cudaGetSymbolAddress((void**)&gbuf,   g_g);
    cudaGetSymbolAddress((void**)&phi,    g_phi);
    cudaGetSymbolAddress((void**)&pwpart, g_pwpart);
    cudaGetSymbolAddress((void**)&pw,     g_pw);
    cudaGetSymbolAddress((void**)&yb,     g_yb);

    const int WSZ = CINT * CIN;             // 524288 per weight matrix
    __nv_bfloat16* wtb = wb + 0 * WSZ;      // theta
    __nv_bfloat16* wgb = wb + 1 * WSZ;      // g
    __nv_bfloat16* wpb = wb + 2 * WSZ;      // phi
    __nv_bfloat16* wob = wb + 3 * WSZ;      // out

    // conversions
    const int nx = NB * CIN * PP;           // 37748736
    f2bf_kernel<<<nx / (256 * 8), 256>>>(x,     xb,    nx);
    f2bf_kernel<<<nx / (256 * 8), 256>>>(x_ref, xrefb, nx);
    f2bf_kernel<<<WSZ / (256 * 8), 256>>>(w_theta, wtb, WSZ);
    f2bf_kernel<<<WSZ / (256 * 8), 256>>>(w_g,     wgb, WSZ);
    f2bf_kernel<<<WSZ / (256 * 8), 256>>>(w_phi,   wpb, WSZ);
    f2bf_kernel<<<WSZ / (256 * 8), 256>>>(w_out,   wob, WSZ);

    // 1x1 convs (tensor-core GEMMs)
    dim3 blk(256);
    dim3 gg1(PP / 128, CINT / 128, NB);     // (72, 4, 4)
    bgemm_kernel<<<gg1, blk>>>(wtb, xb,    b_theta, nullptr, theta, CINT, CIN, PP);
    bgemm_kernel<<<gg1, blk>>>(wgb, xrefb, b_g,     nullptr, gbuf,  CINT, CIN, PP);
    bgemm_kernel<<<gg1, blk>>>(wpb, xrefb, b_phi,   nullptr, phi,   CINT, CIN, PP);

    // correlation partials + softmax
    dim3 cg(WW / CTW, HH / CTH, NB * CSPLIT);   // (3, 12, 16)
    corr_kernel<<<cg, blk>>>(theta, phi, pwpart);
    softmax_kernel<<<(NB * PP) / 128, 128>>>(pwpart, pw);

    // assemble (bf16 output)
    dim3 ag(WW / CTW, HH / CTH, NB * ASPLIT);   // (3, 12, 32)
    assemble_kernel<<<ag, blk>>>(pw, gbuf, yb);

    // final conv + residual
    dim3 gg2(PP / 128, CIN / 128, NB);          // (72, 8, 4)
    bgemm_kernel<<<gg2, blk>>>(wob, yb, b_out, x, out, CIN, CINT, PP);
}

// round 5
// speedup vs baseline: 4.5300x; 1.0950x over previous
#include <cuda_runtime.h>
#include <cuda_bf16.h>
#include <math.h>
#include <stdint.h>

// Problem constants
#define NB    4
#define CIN   1024
#define CINT  512
#define HH    96
#define WW    96
#define PP    (HH * WW)      // 9216
#define DD    4
#define QQ    81
#define CSPLIT 2             // corr channel split
#define ASPLIT 8             // assemble channel split

// ---------------------------------------------------------------------------
// Scratch (device globals; no allocation allowed)
// ---------------------------------------------------------------------------
__device__ __align__(128) __nv_bfloat16 g_xb   [NB * CIN  * PP];
__device__ __align__(128) __nv_bfloat16 g_xrefb[NB * CIN  * PP];
__device__ __align__(128) __nv_bfloat16 g_wb   [4 * CINT * CIN];   // theta,g,phi,out
__device__ __align__(128) float g_theta [NB * CINT * PP];
__device__ __align__(128) float g_g     [NB * CINT * PP];
__device__ __align__(128) float g_phi   [NB * CINT * PP];
__device__ __align__(128) float g_pwpart[CSPLIT * NB * QQ * PP];
__device__ __align__(128) float g_pw    [NB * QQ * PP];
__device__ __align__(128) __nv_bfloat16 g_yb   [NB * CINT * PP];

// ---------------------------------------------------------------------------
// Helpers (legacy-path: cp.async + ldmatrix + mma.sync only; no tcgen05 —
// this toolchain targets sm_103 without the 'a' feature set)
// ---------------------------------------------------------------------------
__device__ __forceinline__ uint32_t sptr(const void* p) {
    return (uint32_t)__cvta_generic_to_shared(p);
}
__device__ __forceinline__ void cp16(uint32_t dst, const void* src) {
    asm volatile("cp.async.cg.shared.global [%0], [%1], 16;" :: "r"(dst), "l"(src));
}
__device__ __forceinline__ void cp_commit() {
    asm volatile("cp.async.commit_group;");
}
__device__ __forceinline__ void cp_wait0() {
    asm volatile("cp.async.wait_group 0;");
}
__device__ __forceinline__ void ldsmx4(uint32_t* r, uint32_t addr) {
    asm volatile("ldmatrix.sync.aligned.m8n8.x4.shared.b16 {%0,%1,%2,%3}, [%4];"
                 : "=r"(r[0]), "=r"(r[1]), "=r"(r[2]), "=r"(r[3]) : "r"(addr));
}
__device__ __forceinline__ void ldsmx4t(uint32_t* r, uint32_t addr) {
    asm volatile("ldmatrix.sync.aligned.m8n8.x4.trans.shared.b16 {%0,%1,%2,%3}, [%4];"
                 : "=r"(r[0]), "=r"(r[1]), "=r"(r[2]), "=r"(r[3]) : "r"(addr));
}
__device__ __forceinline__ void mma16816(float* c, const uint32_t* a, const uint32_t* b) {
    asm volatile("mma.sync.aligned.m16n8k16.row.col.f32.bf16.bf16.f32 "
                 "{%0,%1,%2,%3}, {%4,%5,%6,%7}, {%8,%9}, {%0,%1,%2,%3};"
                 : "+f"(c[0]), "+f"(c[1]), "+f"(c[2]), "+f"(c[3])
                 : "r"(a[0]), "r"(a[1]), "r"(a[2]), "r"(a[3]), "r"(b[0]), "r"(b[1]));
}

// ---------------------------------------------------------------------------
// fp32 -> bf16 conversion (n multiple of 8)
// ---------------------------------------------------------------------------
__global__ void __launch_bounds__(256)
f2bf_kernel(const float* __restrict__ in, __nv_bfloat16* __restrict__ out, int n)
{
    int i = (blockIdx.x * 256 + threadIdx.x) * 8;
    if (i >= n) return;
    float4 v0 = *(const float4*)(in + i);
    float4 v1 = *(const float4*)(in + i + 4);
    __nv_bfloat162 o[4];
    o[0] = __floats2bfloat162_rn(v0.x, v0.y);
    o[1] = __floats2bfloat162_rn(v0.z, v0.w);
    o[2] = __floats2bfloat162_rn(v1.x, v1.y);
    o[3] = __floats2bfloat162_rn(v1.z, v1.w);
    *(uint4*)(out + i) = *(const uint4*)o;
}

// ---------------------------------------------------------------------------
// bf16 tensor-core GEMM (mma.sync):
// O[b][m][p] = sum_k W[m][k]*Z[b][k][p] + bias[m] (+ res[b][m][p])
// BM=BN=128, BK=32, 8 warps (2m x 4n), warp tile 64x32.
// ---------------------------------------------------------------------------
#define AS_STRIDE 40
#define BS_STRIDE 136
#define AS_ELEMS (128 * AS_STRIDE)
#define BS_ELEMS (32 * BS_STRIDE)
#define AS_BYTES (AS_ELEMS * 2)
#define BS_BYTES (BS_ELEMS * 2)

__global__ void __launch_bounds__(256)
bgemm_kernel(const __nv_bfloat16* __restrict__ W, const __nv_bfloat16* __restrict__ Z,
             const float* __restrict__ bias, const float* __restrict__ res,
             float* __restrict__ O, int M, int K, int P)
{
    __shared__ __nv_bfloat16 As[2 * AS_ELEMS];
    __shared__ __nv_bfloat16 Bs[2 * BS_ELEMS];

    const int b  = blockIdx.z;
    const __nv_bfloat16* Zb = Z + (size_t)b * K * P;
    float*       Ob = O + (size_t)b * M * P;
    const float* Rb = res ? res + (size_t)b * M * P : nullptr;

    const int m0 = blockIdx.y * 128;
    const int n0 = blockIdx.x * 128;
    const int tid  = threadIdx.x;
    const int lane = tid & 31;
    const int wid  = tid >> 5;
    const int wm = wid & 1;
    const int wn = wid >> 1;

    const uint32_t as0 = sptr(As);
    const uint32_t bs0 = sptr(Bs);

    const int a_r = tid >> 2;
    const int a_c = tid & 3;
    const int b_r = tid >> 4;
    const int b_c = tid & 15;

    float acc[4][4][4];
#pragma unroll
    for (int mt = 0; mt < 4; mt++)
#pragma unroll
        for (int nt = 0; nt < 4; nt++)
#pragma unroll
            for (int i = 0; i < 4; i++) acc[mt][nt][i] = 0.f;

    const int nk = K >> 5;

    {
        const int k0 = 0;
        cp16(as0 + (uint32_t)((a_r)      * AS_STRIDE + a_c * 8) * 2, W  + (size_t)(m0 + a_r)      * K + k0 + a_c * 8);
        cp16(as0 + (uint32_t)((a_r + 64) * AS_STRIDE + a_c * 8) * 2, W  + (size_t)(m0 + a_r + 64) * K + k0 + a_c * 8);
        cp16(bs0 + (uint32_t)((b_r)      * BS_STRIDE + b_c * 8) * 2, Zb + (size_t)(k0 + b_r)      * P + n0 + b_c * 8);
        cp16(bs0 + (uint32_t)((b_r + 16) * BS_STRIDE + b_c * 8) * 2, Zb + (size_t)(k0 + b_r + 16) * P + n0 + b_c * 8);
        cp_commit();
    }

    int stage = 0;
    for (int kt = 0; kt < nk; kt++) {
        cp_wait0();
        __syncthreads();

        if (kt + 1 < nk) {
            const int k0 = (kt + 1) * 32;
            const uint32_t as = as0 + (stage ^ 1) * AS_BYTES;
            const uint32_t bs = bs0 + (stage ^ 1) * BS_BYTES;
            cp16(as + (uint32_t)((a_r)      * AS_STRIDE + a_c * 8) * 2, W  + (size_t)(m0 + a_r)      * K + k0 + a_c * 8);
            cp16(as + (uint32_t)((a_r + 64) * AS_STRIDE + a_c * 8) * 2, W  + (size_t)(m0 + a_r + 64) * K + k0 + a_c * 8);
            cp16(bs + (uint32_t)((b_r)      * BS_STRIDE + b_c * 8) * 2, Zb + (size_t)(k0 + b_r)      * P + n0 + b_c * 8);
            cp16(bs + (uint32_t)((b_r + 16) * BS_STRIDE + b_c * 8) * 2, Zb + (size_t)(k0 + b_r + 16) * P + n0 + b_c * 8);
            cp_commit();
        }

        const uint32_t as = as0 + stage * AS_BYTES;
        const uint32_t bs = bs0 + stage * BS_BYTES;

#pragma unroll
        for (int kk = 0; kk < 2; kk++) {
            const int k0 = kk * 16;
            uint32_t a[4][4];
            const uint32_t a_base = as + (uint32_t)(((wm * 64 + (lane & 15)) * AS_STRIDE) + k0 + (lane >> 4) * 8) * 2;
#pragma unroll
            for (int mt = 0; mt < 4; mt++)
                ldsmx4(a[mt], a_base + (uint32_t)(mt * 16 * AS_STRIDE) * 2);

            uint32_t bb[4][2];
            const uint32_t b_base = bs + (uint32_t)((k0 + (lane & 15)) * BS_STRIDE + wn * 32 + (lane >> 4) * 8) * 2;
            {
                uint32_t r[4];
                ldsmx4t(r, b_base);
                bb[0][0] = r[0]; bb[0][1] = r[1];
                bb[1][0] = r[2]; bb[1][1] = r[3];
                ldsmx4t(r, b_base + 16 * 2);
                bb[2][0] = r[0]; bb[2][1] = r[1];
                bb[3][0] = r[2]; bb[3][1] = r[3];
            }

#pragma unroll
            for (int mt = 0; mt < 4; mt++)
#pragma unroll
                for (int nt = 0; nt < 4; nt++)
                    mma16816(acc[mt][nt], a[mt], bb[nt]);
        }
        stage ^= 1;
        __syncthreads();
    }

#pragma unroll
    for (int mt = 0; mt < 4; mt++) {
        const int r0 = m0 + wm * 64 + mt * 16 + (lane >> 2);
        const int r1 = r0 + 8;
        const float bv0 = bias[r0];
        const float bv1 = bias[r1];
#pragma unroll
        for (int nt = 0; nt < 4; nt++) {
            const int col = n0 + wn * 32 + nt * 8 + (lane & 3) * 2;
            float2 v0 = make_float2(acc[mt][nt][0] + bv0, acc[mt][nt][1] + bv0);
            float2 v1 = make_float2(acc[mt][nt][2] + bv1, acc[mt][nt][3] + bv1);
            if (Rb) {
                float2 t0 = *(const float2*)&Rb[(size_t)r0 * P + col];
                float2 t1 = *(const float2*)&Rb[(size_t)r1 * P + col];
                v0.x += t0.x; v0.y += t0.y;
                v1.x += t1.x; v1.y += t1.y;
            }
            *(float2*)&Ob[(size_t)r0 * P + col] = v0;
            *(float2*)&Ob[(size_t)r1 * P + col] = v1;
        }
    }
}

// ---------------------------------------------------------------------------
// Correlation, 2-pixel y-blocking.
// Tile: 32 (w) x 16 (h) pixels; thread (tx,ty) handles pixels (2ty, tx) and
// (2ty+1, tx). Their windows share 8 of 10 rows -> 90 smem reads / 162 FMAs.
// CSPLIT=2 channel split -> grid 3 x 6 x 8 = 144 blocks (one full wave).
// ---------------------------------------------------------------------------
#define CTW 32
#define CTH2 16
#define CWW (CTW + 2 * DD)    // 40
#define CWH (CTH2 + 2 * DD)   // 24
#define CCH 8
#define CPB (CINT / CSPLIT)   // 256

__global__ void __launch_bounds__(256, 1)
corr_kernel(const float* __restrict__ theta,
            const float* __restrict__ phi,
            float* __restrict__ pwpart)
{
    __shared__ float th_s[CCH * CTH2 * CTW];   // 16 KB
    __shared__ float ph_s[CCH * CWH * CWW];    // 30 KB

    const int z  = blockIdx.z;
    const int b  = z >> 1;
    const int ci = z & 1;
    const int ch0 = ci * CPB;
    const int w0 = blockIdx.x * CTW;
    const int h0 = blockIdx.y * CTH2;
    const int tid = threadIdx.x;
    const int tx = tid & 31;
    const int ty = tid >> 5;          // 0..7 -> pixel rows 2ty, 2ty+1

    const float* thb = theta + (size_t)b * CINT * PP;
    const float* phb = phi   + (size_t)b * CINT * PP;

    float accA[QQ], accB[QQ];
#pragma unroll
    for (int q = 0; q < QQ; q++) { accA[q] = 0.f; accB[q] = 0.f; }

    for (int c0 = ch0; c0 < ch0 + CPB; c0 += CCH) {
        // theta tile: CCH x 16 x 32 = 4096 floats
#pragma unroll
        for (int ii = 0; ii < (CCH * CTH2 * CTW) / 256; ii++) {
            const int i   = tid + ii * 256;
            const int cc  = i >> 9;            // /512
            const int rem = i & 511;
            th_s[i] = thb[(size_t)(c0 + cc) * PP + (h0 + (rem >> 5)) * WW + (w0 + (rem & 31))];
        }
        // phi window: CCH x 24 x 40 = 7680 floats, zero-padded
#pragma unroll
        for (int ii = 0; ii < (CCH * CWH * CWW) / 256; ii++) {
            const int i   = tid + ii * 256;
            const int cc  = i / (CWH * CWW);
            const int rem = i % (CWH * CWW);
            const int r   = rem / CWW;
            const int col = rem % CWW;
            const int hh = h0 - DD + r;
            const int ww = w0 - DD + col;
            float v = 0.f;
            if (hh >= 0 && hh < HH && ww >= 0 && ww < WW)
                v = phb[(size_t)(c0 + cc) * PP + hh * WW + ww];
            ph_s[i] = v;
        }
        __syncthreads();

#pragma unroll
        for (int cc = 0; cc < CCH; cc++) {
            const float t0 = th_s[cc * (CTH2 * CTW) + (2 * ty)     * CTW + tx];
            const float t1 = th_s[cc * (CTH2 * CTW) + (2 * ty + 1) * CTW + tx];
            const float* pr = &ph_s[cc * (CWH * CWW)];
#pragma unroll
            for (int rr = 0; rr < 10; rr++) {
                const float* row = &pr[(2 * ty + rr) * CWW + tx];
#pragma unroll
                for (int dx = 0; dx < 9; dx++) {
                    const float v = row[dx];
                    if (rr < 9) accA[rr * 9 + dx] += t0 * v;
                    if (rr >= 1) accB[(rr - 1) * 9 + dx] += t1 * v;
                }
            }
        }
        __syncthreads();
    }

    const int pixA = (h0 + 2 * ty) * WW + (w0 + tx);
    float* bp = pwpart + ((size_t)(ci * NB + b) * QQ) * PP;
#pragma unroll
    for (int q = 0; q < QQ; q++) {
        bp[(size_t)q * PP + pixA]      = accA[q];
        bp[(size_t)q * PP + pixA + WW] = accB[q];
    }
}

// ---------------------------------------------------------------------------
// Softmax over Q (sums the 2 channel-split partials, applies scale)
// ---------------------------------------------------------------------------
__global__ void __launch_bounds__(128)
softmax_kernel(const float* __restrict__ part, float* __restrict__ pw)
{
    const int t = blockIdx.x * 128 + threadIdx.x;
    const int b = t / PP;
    const int pix = t - b * PP;
    const size_t qp = (size_t)QQ * PP;
    const float scale = 256.0f / sqrtf((float)WW) / (float)CINT;

    float v[QQ];
    float m = -1e30f;
#pragma unroll
    for (int q = 0; q < QQ; q++) {
        const size_t off = (size_t)q * PP + pix;
        float s = part[(size_t)(0 * NB + b) * qp + off]
                + part[(size_t)(1 * NB + b) * qp + off];
        v[q] = s * scale;
        m = fmaxf(m, v[q]);
    }
    float s = 0.f;
#pragma unroll
    for (int q = 0; q < QQ; q++) { v[q] = __expf(v[q] - m); s += v[q]; }
    const float inv = 1.0f / s;
    float* pwb = pw + (size_t)b * qp + pix;
#pragma unroll
    for (int q = 0; q < QQ; q++) pwb[(size_t)q * PP] = v[q] * inv;
}

// ---------------------------------------------------------------------------
// Assemble, 2-pixel y-blocking: y[b][c][p] = sum_q pw[b][q][p]*g window.
// Same tiling as corr; pw (2x81) in registers, g window rows shared.
// ---------------------------------------------------------------------------
__global__ void __launch_bounds__(256, 1)
assemble_kernel(const float* __restrict__ pw,
                const float* __restrict__ g,
                __nv_bfloat16* __restrict__ y)
{
    __shared__ float gs[CCH * CWH * CWW];   // 30 KB

    const int z  = blockIdx.z;
    const int b  = z >> 3;
    const int c0base = (z & 7) * (CINT / ASPLIT); // 64 channels
    const int w0 = blockIdx.x * CTW;
    const int h0 = blockIdx.y * CTH2;
    const int tid = threadIdx.x;
    const int tx = tid & 31;
    const int ty = tid >> 5;

    const float* gb  = g  + (size_t)b * CINT * PP;
    const float* pwb = pw + (size_t)b * QQ * PP;
    __nv_bfloat16* yb = y + (size_t)b * CINT * PP;

    const int pixA = (h0 + 2 * ty) * WW + (w0 + tx);
    const int pixB = pixA + WW;

    float rpwA[QQ], rpwB[QQ];
#pragma unroll
    for (int q = 0; q < QQ; q++) {
        rpwA[q] = pwb[(size_t)q * PP + pixA];
        rpwB[q] = pwb[(size_t)q * PP + pixB];
    }

    for (int c0 = c0base; c0 < c0base + CINT / ASPLIT; c0 += CCH) {
#pragma unroll
        for (int ii = 0; ii < (CCH * CWH * CWW) / 256; ii++) {
            const int i   = tid + ii * 256;
            const int cc  = i / (CWH * CWW);
            const int rem = i % (CWH * CWW);
            const int r   = rem / CWW;
            const int col = rem % CWW;
            const int hh = h0 - DD + r;
            const int ww = w0 - DD + col;
            float v = 0.f;
            if (hh >= 0 && hh < HH && ww >= 0 && ww < WW)
                v = gb[(size_t)(c0 + cc) * PP + hh * WW + ww];
            gs[i] = v;
        }
        __syncthreads();

#pragma unroll
        for (int cc = 0; cc < CCH; cc++) {
            const float* gr = &gs[cc * (CWH * CWW)];
            float aA = 0.f, aB = 0.f;
#pragma unroll
            for (int rr = 0; rr < 10; rr++) {
                const float* row = &gr[(2 * ty + rr) * CWW + tx];
#pragma unroll
                for (int dx = 0; dx < 9; dx++) {
                    const float v = row[dx];
                    if (rr < 9) aA += rpwA[rr * 9 + dx] * v;
                    if (rr >= 1) aB += rpwB[(rr - 1) * 9 + dx] * v;
                }
            }
            yb[(size_t)(c0 + cc) * PP + pixA] = __float2bfloat16(aA);
            yb[(size_t)(c0 + cc) * PP + pixB] = __float2bfloat16(aB);
        }
        __syncthreads();
    }
}

// ---------------------------------------------------------------------------
// Launch
// ---------------------------------------------------------------------------
extern "C" void kernel_launch(void* const* d_in, const int* in_sizes, int n_in,
                              void* d_out, int out_size)
{
    (void)in_sizes; (void)n_in; (void)out_size;

    const float* x       = (const float*)d_in[0];
    const float* x_ref   = (const float*)d_in[1];
    const float* w_g     = (const float*)d_in[2];
    const float* b_g     = (const float*)d_in[3];
    const float* w_theta = (const float*)d_in[4];
    const float* b_theta = (const float*)d_in[5];
    const float* w_phi   = (const float*)d_in[6];
    const float* b_phi   = (const float*)d_in[7];
    const float* w_out   = (const float*)d_in[8];
    const float* b_out   = (const float*)d_in[9];
    float* out = (float*)d_out;

    __nv_bfloat16 *xb, *xrefb, *wb, *yb;
    float *theta, *gbuf, *phi, *pwpart, *pw;
    cudaGetSymbolAddress((void**)&xb,     g_xb);
    cudaGetSymbolAddress((void**)&xrefb,  g_xrefb);
    cudaGetSymbolAddress((void**)&wb,     g_wb);
    cudaGetSymbolAddress((void**)&theta,  g_theta);
    cudaGetSymbolAddress((void**)&gbuf,   g_g);
    cudaGetSymbolAddress((void**)&phi,    g_phi);
    cudaGetSymbolAddress((void**)&pwpart, g_pwpart);
    cudaGetSymbolAddress((void**)&pw,     g_pw);
    cudaGetSymbolAddress((void**)&yb,     g_yb);

    const int WSZ = CINT * CIN;
    __nv_bfloat16* wtb = wb + 0 * WSZ;
    __nv_bfloat16* wgb = wb + 1 * WSZ;
    __nv_bfloat16* wpb = wb + 2 * WSZ;
    __nv_bfloat16* wob = wb + 3 * WSZ;

    // conversions
    const int nx = NB * CIN * PP;
    f2bf_kernel<<<nx / (256 * 8), 256>>>(x,     xb,    nx);
    f2bf_kernel<<<nx / (256 * 8), 256>>>(x_ref, xrefb, nx);
    f2bf_kernel<<<WSZ / (256 * 8), 256>>>(w_theta, wtb, WSZ);
    f2bf_kernel<<<WSZ / (256 * 8), 256>>>(w_g,     wgb, WSZ);
    f2bf_kernel<<<WSZ / (256 * 8), 256>>>(w_phi,   wpb, WSZ);
    f2bf_kernel<<<WSZ / (256 * 8), 256>>>(w_out,   wob, WSZ);

    // 1x1 convs (tensor-core GEMMs, legacy mma.sync path)
    dim3 blk(256);
    dim3 gg1(PP / 128, CINT / 128, NB);     // (72, 4, 4)
    bgemm_kernel<<<gg1, blk>>>(wtb, xb,    b_theta, nullptr, theta, CINT, CIN, PP);
    bgemm_kernel<<<gg1, blk>>>(wgb, xrefb, b_g,     nullptr, gbuf,  CINT, CIN, PP);
    bgemm_kernel<<<gg1, blk>>>(wpb, xrefb, b_phi,   nullptr, phi,   CINT, CIN, PP);

    // correlation partials (2-pixel y-blocked) + softmax
    dim3 cg(WW / CTW, HH / CTH2, NB * CSPLIT);   // (3, 6, 8) = 144 blocks
    corr_kernel<<<cg, blk>>>(theta, phi, pwpart);
    softmax_kernel<<<(NB * PP) / 128, 128>>>(pwpart, pw);

    // assemble (2-pixel y-blocked, bf16 output)
    dim3 ag(WW / CTW, HH / CTH2, NB * ASPLIT);   // (3, 6, 32) = 576 blocks
    assemble_kernel<<<ag, blk>>>(pw, gbuf, yb);

    // final conv + residual
    dim3 gg2(PP / 128, CIN / 128, NB);           // (72, 8, 4)
    bgemm_kernel<<<gg2, blk>>>(wob, yb, b_out, x, out, CIN, CINT, PP);
}